// round 8
// baseline (speedup 1.0000x reference)
#include <cuda_runtime.h>
#include <math.h>

// ChfLoss: B=8, H=W=64, P=60. loss = (0.1/B) * sum_b ||CHF(dnn_b - gt_b)||_2
// Separable trig: angle[p,q,(i,j)] = r_q*x_i + r_p*y_j, x_axis == y_axis.
// ONE kernel. Trig table built per block via complex ROTATION RECURRENCE
// (4 FMA/entry) instead of per-entry sincos: 480 MUFU ops/block vs 7680,
// which was the measured bottleneck (MUFU rt=8 -> 15360 cyc = 8.5us).

#define NB      8
#define HWD     64
#define PP      60
#define PTILES  15                  // 60 / 4 p-rows per block
#define NBLK    (NB * PTILES)       // 120
#define NT      512

// __device__ globals = sanctioned scratch (no allocation allowed)
__device__ float    g_part[NBLK];         // per-block partial sum of squares
__device__ unsigned g_count = 0;          // epilogue counter (self-resetting)

// Shared: D 4096 + CS 7680 + A 512 = 12288 floats = 48KB dynamic exactly.
// NO static __shared__ anywhere (would exceed the 48KB default limit).
__global__ __launch_bounds__(NT) void chf_fused_kernel(const float* __restrict__ dnn,
                                                       const float* __restrict__ gt,
                                                       float* __restrict__ out) {
    extern __shared__ float sm[];
    float*  sD  = sm;                               // [j*64 + i]
    float2* sCS = (float2*)(sm + 4096);             // [i*60 + q] (also [j*60 + p])
    float2* sA  = (float2*)(sm + 4096 + 7680);      // [i*4 + pl]

    const int blk = blockIdx.x;
    const int b   = blk / PTILES;
    const int pt  = blk - b * PTILES;
    const int p0  = pt * 4;
    const int t   = threadIdx.x;
    const int tt   = t >> 1;                        // pair index
    const int half = t & 1;                         // which half of inner loop

    // ---- issue global loads FIRST (latency hidden by table gen below) ----
    const float4* d4 = (const float4*)(dnn + b * 4096);
    const float4* g4 = (const float4*)(gt  + b * 4096);
    float4 va[2], vg[2];
    #pragma unroll
    for (int k = 0; k < 2; k++) {
        va[k] = d4[t + k * NT];
        vg[k] = g4[t + k * NT];
    }

    // ---- trig table via rotation recurrence: threads 0..119, 2 per q ----
    // Ref angle a_i = fl(r_q * x_i), x_i = 4+8i. Recurrence tracks trig of the
    // EXACT real product theta_i = r_q*x_i (base from two-float hi+lo, step
    // rotation by w=8r), then per entry corrects by d = a_i - theta_i = -lo_i
    // (computable exactly via fma): cos(a)=c+lo*s, sin(a)=s-lo*c to ~1e-8.
    if (t < 2 * PP) {
        const float inv2pi = 0.15915494309189535f;
        const float C1 = 6.28125f;                   // 201/32, exact fp32 products
        const float C2 = 1.9353071795864769e-3f;     // 2*pi - C1
        const int q   = t >> 1;
        const int i0  = (t & 1) * 32;
        const float r = (float)(q - 30) * 0.1f;      // fp32 grid, matches ref

        // base: trig of exact real r*x_{i0}
        float x0 = (float)(4 + 8 * i0);
        float hi = r * x0;
        float lo0 = fmaf(r, x0, -hi);                // exact residual
        float kb = rintf(hi * inv2pi);
        float ab = fmaf(-kb, C1, hi);                // exact (Cody-Waite)
        ab = fmaf(-kb, C2, ab) + lo0;                // trig arg of hi+lo0
        float c, s;
        __sincosf(ab, &s, &c);

        // step rotation: trig of exact w = 8*r (exact fp32)
        float w  = 8.0f * r;
        float kw = rintf(w * inv2pi);
        float aw = fmaf(-kw, C1, w);                 // exact
        aw = fmaf(-kw, C2, aw);
        float sw, cw;
        __sincosf(aw, &sw, &cw);

        #pragma unroll 8
        for (int ii = 0; ii < 32; ii++) {
            int i = i0 + ii;
            float x  = (float)(4 + 8 * i);
            float a  = r * x;                        // ref's fp32 angle
            float lo = fmaf(r, x, -a);               // theta - a, exact
            // correct to ref's rounded angle (1st order, |lo| <= 9e-5)
            sCS[i * PP + q] = make_float2(fmaf(lo, s, c), fmaf(-lo, c, s));
            // rotate by w
            float cn = fmaf(c, cw, -s * sw);
            s        = fmaf(s, cw,  c * sw);
            c = cn;
        }
    }

    // ---- D = dnn - gt into shared ----
    {
        float4* sD4 = (float4*)sD;
        #pragma unroll
        for (int k = 0; k < 2; k++) {
            sD4[t + k * NT] = make_float4(va[k].x - vg[k].x, va[k].y - vg[k].y,
                                          va[k].z - vg[k].z, va[k].w - vg[k].w);
        }
    }
    __syncthreads();

    // ---- stage 1: pair tt -> (pl = tt>>6, i = tt&63); halves split j ----
    {
        const int pl = tt >> 6;                      // uniform per warp
        const int i  = tt & 63;
        const int p  = p0 + pl;
        const int j0 = half * 32;
        float ac = 0.f, as = 0.f;
        #pragma unroll 16
        for (int jj = 0; jj < 32; jj++) {
            int j = j0 + jj;
            float  d  = sD[j * 64 + i];      // paired broadcast, conflict-free
            float2 cs = sCS[j * PP + p];     // 2 addrs/warp, broadcast
            ac = fmaf(cs.x, d, ac);
            as = fmaf(cs.y, d, as);
        }
        ac += __shfl_xor_sync(0xFFFFFFFFu, ac, 1);   // a+b both lanes: exact, det.
        as += __shfl_xor_sync(0xFFFFFFFFu, as, 1);
        if (!half) sA[i * 4 + pl] = make_float2(ac, as);
    }
    __syncthreads();

    // ---- stage 2: pairs 0..239 -> (pl = tt/60, q = tt%60); halves split i ----
    float re = 0.f, im = 0.f;
    if (tt < 240) {
        const int pl = tt / 60;
        const int q  = tt - pl * 60;
        const int i0 = half * 32;
        float re1 = 0.f, re2 = 0.f, im1 = 0.f, im2 = 0.f;
        #pragma unroll 16
        for (int ii = 0; ii < 32; ii++) {
            int i = i0 + ii;
            float2 a  = sA[i * 4 + pl];      // broadcast
            float2 cs = sCS[i * PP + q];
            re1 = fmaf(a.x, cs.x, re1);
            re2 = fmaf(a.y, cs.y, re2);
            im1 = fmaf(a.y, cs.x, im1);
            im2 = fmaf(a.x, cs.y, im2);
        }
        re = re1 - re2;
        im = im1 + im2;
    }
    re += __shfl_xor_sync(0xFFFFFFFFu, re, 1);       // combine halves (exact)
    im += __shfl_xor_sync(0xFFFFFFFFu, im, 1);
    float v = (!half && tt < 240) ? fmaf(re, re, im * im) : 0.f;

    // ---- block reduce sum of squares ----
    #pragma unroll
    for (int off = 16; off > 0; off >>= 1)
        v += __shfl_down_sync(0xFFFFFFFFu, v, off);

    __syncthreads();                       // stage-2 smem reads done; reuse sD
    if ((t & 31) == 0) sD[t >> 5] = v;     // 16 warp partials
    __syncthreads();
    if (t == 0) {
        float s = 0.f;
        #pragma unroll
        for (int w = 0; w < 16; w++) s += sD[w];
        g_part[blk] = s;
        __threadfence();                   // release g_part before counter bump
        unsigned c = atomicAdd(&g_count, 1u);
        bool last = (c == NBLK - 1);
        if (last) g_count = 0;             // reset for next graph replay
        sD[16] = last ? 1.f : 0.f;         // flag via dynamic smem (no static shared)
    }
    __syncthreads();

    // ---- last block: deterministic finalize ----
    if (sD[16] != 0.f) {
        __threadfence();                   // acquire: all g_part visible
        float w = 0.f;
        if (t < NB) {
            float s = 0.f;
            #pragma unroll
            for (int k = 0; k < PTILES; k++)
                s += g_part[t * PTILES + k];   // fixed order -> deterministic
            w = sqrtf(s);
        }
        if (t < 32) {
            #pragma unroll
            for (int off = 16; off > 0; off >>= 1)
                w += __shfl_down_sync(0xFFFFFFFFu, w, off);
            if (t == 0) out[0] = w * 0.1f / 8.0f;
        }
    }
}

// ---------------------------------------------------------------------------
extern "C" void kernel_launch(void* const* d_in, const int* in_sizes, int n_in,
                              void* d_out, int out_size) {
    (void)in_sizes; (void)n_in; (void)out_size;
    const float* dnn = (const float*)d_in[0];
    const float* gt  = (const float*)d_in[1];
    float* out = (float*)d_out;

    chf_fused_kernel<<<NBLK, NT, 12288 * sizeof(float)>>>(dnn, gt, out);
}